// round 14
// baseline (speedup 1.0000x reference)
#include <cuda_runtime.h>
#include <cuda_fp16.h>
#include <cstdint>

// ---------------------------------------------------------------------------
// BasisConvLayer (mode='conv', linear hat basis 4x4, F_in=F_out=16)
//
// FP16 table  T[node][u:4][v:4][fout:16]  (512 B/node, 51 MB).
//   Kernel 1 (build) = GEMM X[100K,16] @ W'[16,256] via mma.sync.m16n8k16
//     (fp16 in, fp32 acc). One 64-node group per block (grid covers all
//     nodes in a single iteration -> cross-block latency overlap).
//     Also zeroes the output buffer (folds the memset launch away).
//   Kernel 2 (edge): proven 38.4us config: 4 lanes/edge x 2 edges/thread;
//     2 LDG.128/lane; split shfl_xor(2) combine; red.global.add.v4.
// ---------------------------------------------------------------------------

#define MAX_NODES 100000
#define F 16
#define TROWH 256                 // halves per node

__device__ __align__(512) __half g_table[(size_t)MAX_NODES * TROWH];

// memory halves order [lo, hi]
#define CVT_F16X2(u, lo, hi) \
    asm("cvt.rn.f16x2.f32 %0, %1, %2;" : "=r"(u) : "f"(hi), "f"(lo))

// ---------------------------------------------------------------------------
// Kernel 1: tensor-core build + output zeroing.
// ---------------------------------------------------------------------------
#define OROW 528                    // padded smem row bytes
#define OTILE (16 * OROW)           // 8448 B per M-tile

__global__ __launch_bounds__(256) void build_table_kernel(
    const float* __restrict__ x,
    const float* __restrict__ w,
    float4* __restrict__ out4,
    int out_n4,
    int n_nodes)
{
    __shared__ __align__(16) char smemA[4 * 512];     // 4 tiles x 16x16 fp16
    __shared__ __align__(16) char smemO[4 * OTILE];   // 33792 B

    int tid  = threadIdx.x;
    int lane = tid & 31;
    int wrp  = tid >> 5;
    int m    = wrp >> 1;            // M-tile slot 0..3
    int h    = wrp & 1;             // n-half: cols h*128 .. h*128+127

    // ---- zero the output buffer (replaces cudaMemsetAsync) ----
    {
        float4 z = make_float4(0.f, 0.f, 0.f, 0.f);
        for (int i = blockIdx.x * 256 + tid; i < out_n4;
             i += gridDim.x * 256)
            out4[i] = z;
    }

    // ---- build B fragments once: 16 n8-tiles for this half ----
    unsigned bf0[16], bf1[16];
    {
        int k0 = (lane & 3) * 2;
#pragma unroll
        for (int t = 0; t < 16; t++) {
            int n    = h * 128 + t * 8 + (lane >> 2);
            int cell = n >> 4;
            int fo   = n & 15;
            const float* wc = w + cell * 256 + fo;
            float f0 = wc[k0 * 16];
            float f1 = wc[(k0 + 1) * 16];
            float f2 = wc[(k0 + 8) * 16];
            float f3 = wc[(k0 + 9) * 16];
            CVT_F16X2(bf0[t], f0, f1);
            CVT_F16X2(bf1[t], f2, f3);
        }
    }

    const float4* xf4 = reinterpret_cast<const float4*>(x);
    uint4* tb4 = reinterpret_cast<uint4*>(g_table);

    int n_tiles = (n_nodes + 15) >> 4;

    for (int bt = blockIdx.x * 4; bt < n_tiles; bt += gridDim.x * 4) {
        // ---- stage x tile: 64 nodes, fp32 -> fp16 ----
        {
            int nloc = tid >> 2;
            int part = tid & 3;
            int node = bt * 16 + nloc;
            uint2 v2 = make_uint2(0u, 0u);
            if (node < n_nodes) {
                float4 v = xf4[(size_t)node * 4 + part];
                CVT_F16X2(v2.x, v.x, v.y);
                CVT_F16X2(v2.y, v.z, v.w);
            }
            *reinterpret_cast<uint2*>(
                smemA + (nloc >> 4) * 512 + (nloc & 15) * 32 + part * 8) = v2;
        }
        __syncthreads();

        // ---- A fragments via ldmatrix.x4 ----
        unsigned a0, a1, a2, a3;
        {
            unsigned sa = (unsigned)__cvta_generic_to_shared(
                smemA + m * 512 + (lane & 15) * 32 + (lane >> 4) * 16);
            asm volatile(
                "ldmatrix.sync.aligned.m8n8.x4.shared.b16 {%0,%1,%2,%3}, [%4];"
                : "=r"(a0), "=r"(a1), "=r"(a2), "=r"(a3) : "r"(sa));
        }

        // ---- 16 HMMA in two halves of 8, pack + STS ----
        char* ob = smemO + m * OTILE;
        int row = lane >> 2;
#pragma unroll
        for (int half = 0; half < 2; half++) {
            float d[8][4];
#pragma unroll
            for (int tt = 0; tt < 8; tt++) {
                int t = half * 8 + tt;
                d[tt][0] = 0.f; d[tt][1] = 0.f; d[tt][2] = 0.f; d[tt][3] = 0.f;
                asm volatile(
                    "mma.sync.aligned.m16n8k16.row.col.f32.f16.f16.f32 "
                    "{%0,%1,%2,%3}, {%4,%5,%6,%7}, {%8,%9}, {%0,%1,%2,%3};"
                    : "+f"(d[tt][0]), "+f"(d[tt][1]),
                      "+f"(d[tt][2]), "+f"(d[tt][3])
                    : "r"(a0), "r"(a1), "r"(a2), "r"(a3),
                      "r"(bf0[t]), "r"(bf1[t]));
            }
#pragma unroll
            for (int tt = 0; tt < 8; tt++) {
                int t  = half * 8 + tt;
                int n0 = h * 128 + t * 8 + (lane & 3) * 2;
                unsigned p01, p23;
                CVT_F16X2(p01, d[tt][0], d[tt][1]);
                CVT_F16X2(p23, d[tt][2], d[tt][3]);
                *reinterpret_cast<unsigned*>(ob + row * OROW + n0 * 2) = p01;
                *reinterpret_cast<unsigned*>(ob + (row + 8) * OROW + n0 * 2) = p23;
            }
        }
        __syncthreads();

        // ---- coalesced readout: smemO -> g_table ----
        {
            int nloc = tid >> 2;
            int j0   = tid & 3;
            int node = bt * 16 + nloc;
            if (node < n_nodes) {
                const char* src = smemO + (nloc >> 4) * OTILE + (nloc & 15) * OROW;
#pragma unroll
                for (int jj = 0; jj < 8; jj++) {
                    int j = j0 + jj * 4;
                    uint4 val = *reinterpret_cast<const uint4*>(src + j * 16);
                    tb4[(size_t)node * 32 + j] = val;
                }
            }
        }
        __syncthreads();
    }
}

// ---------------------------------------------------------------------------
// Kernel 2: edge (proven 38.4us config).
// ---------------------------------------------------------------------------
#define EPB 128
__global__ __launch_bounds__(256) void edge_kernel(
    const int* __restrict__ ei,
    const float* __restrict__ attr,
    float* __restrict__ out,
    int n_edges)
{
    int tid = threadIdx.x;
    int sl  = tid & 3;
    int g   = tid >> 2;

    const uint4* tb = reinterpret_cast<const uint4*>(g_table);

    int  e[2];
    e[0] = (int)(blockIdx.x * EPB) + g;
    e[1] = e[0] + 64;
    bool val[2];
    int  row[2];
    uint4 u0[2], u1[2];
    float wa[2], wb[2];

#pragma unroll
    for (int i = 0; i < 2; i++) {
        val[i] = (e[i] < n_edges);
        int ec = val[i] ? e[i] : (n_edges - 1);

        row[i]   = ei[ec];
        int col  = ei[n_edges + ec];
        float2 a = reinterpret_cast<const float2*>(attr)[ec];

        float sx = fmaf(a.x, 1.5f, 1.5f);
        float sy = fmaf(a.y, 1.5f, 1.5f);
        float ixf = fminf(fmaxf(floorf(sx), 0.f), 2.f);
        float iyf = fminf(fmaxf(floorf(sy), 0.f), 2.f);
        float fx = sx - ixf;
        float fy = sy - iyf;
        int iu = (int)ixf;
        int iv = (int)iyf;

        float w11 = fx * fy;
        float w10 = fx - w11;
        float w01 = fy - w11;
        float w00 = 1.f - fx - fy + w11;

        wa[i] = (sl < 2) ? w00 : w01;   // u = iu
        wb[i] = (sl < 2) ? w10 : w11;   // u = iu+1

        size_t bi = (size_t)col * 32 + (iu * 4 + iv) * 2 + sl;
        u0[i] = tb[bi];
        u1[i] = tb[bi + 8];
    }

#pragma unroll
    for (int i = 0; i < 2; i++) {
        const __half2* h0 = reinterpret_cast<const __half2*>(&u0[i]);
        const __half2* h1 = reinterpret_cast<const __half2*>(&u1[i]);
        float p[8];
#pragma unroll
        for (int j = 0; j < 4; j++) {
            float2 f0 = __half22float2(h0[j]);
            float2 f1 = __half22float2(h1[j]);
            p[2 * j]     = fmaf(wa[i], f0.x, wb[i] * f1.x);
            p[2 * j + 1] = fmaf(wa[i], f0.y, wb[i] * f1.y);
        }
        bool hi = (sl & 2);
        float fin0, fin1, fin2, fin3;
        {
            float s0 = hi ? p[0] : p[4];
            float s1 = hi ? p[1] : p[5];
            float s2 = hi ? p[2] : p[6];
            float s3 = hi ? p[3] : p[7];
            float r0 = __shfl_xor_sync(0xffffffffu, s0, 2);
            float r1 = __shfl_xor_sync(0xffffffffu, s1, 2);
            float r2 = __shfl_xor_sync(0xffffffffu, s2, 2);
            float r3 = __shfl_xor_sync(0xffffffffu, s3, 2);
            fin0 = (hi ? p[4] : p[0]) + r0;
            fin1 = (hi ? p[5] : p[1]) + r1;
            fin2 = (hi ? p[6] : p[2]) + r2;
            fin3 = (hi ? p[7] : p[3]) + r3;
        }
        if (val[i]) {
            int quad = (sl & 1) * 2 + (sl >> 1);
            float* op = out + (size_t)row[i] * F + quad * 4;
            asm volatile("red.global.add.v4.f32 [%0], {%1, %2, %3, %4};"
                         :: "l"(op), "f"(fin0), "f"(fin1), "f"(fin2), "f"(fin3)
                         : "memory");
        }
    }
}

// ---------------------------------------------------------------------------
extern "C" void kernel_launch(void* const* d_in, const int* in_sizes, int n_in,
                              void* d_out, int out_size)
{
    const float* x    = (const float*)d_in[0];
    const int*   ei   = (const int*)d_in[1];
    const float* attr = (const float*)d_in[2];
    const float* w    = (const float*)d_in[3];
    float*       out  = (float*)d_out;

    int n_nodes = in_sizes[0] / F;       // 100000
    int n_edges = in_sizes[1] / 2;       // 1600000

    int n_tiles  = (n_nodes + 15) / 16;       // 6250
    int bt_grid  = (n_tiles + 3) / 4;         // 1563 -> single iteration
    build_table_kernel<<<bt_grid, 256>>>(x, w, (float4*)out,
                                         out_size / 4, n_nodes);

    int ek_blocks = (n_edges + EPB - 1) / EPB;
    edge_kernel<<<ek_blocks, 256>>>(ei, attr, out, n_edges);
}

// round 15
// speedup vs baseline: 1.1197x; 1.1197x over previous
#include <cuda_runtime.h>
#include <cuda_fp16.h>
#include <cstdint>

// ---------------------------------------------------------------------------
// BasisConvLayer (mode='conv', linear hat basis 4x4, F_in=F_out=16)
//
// FP16 table  T[node][u:4][v:4][fout:16]  (512 B/node, 51 MB).
//   Kernel 0 (wfrag): precompute HMMA B-fragments (fp16) into an 8 KB global
//     buffer, lane-interleaved -> consumers fetch with 8 coalesced LDG.128.
//   Kernel 1 (build) = GEMM X[100K,16] @ W'[16,256] via mma.sync.m16n8k16;
//     grid covers all 16-node tiles in ONE iteration (latency overlap across
//     ~10 blocks/SM). Also zeroes the output buffer.
//   Kernel 2 (edge): proven 38.4us config: 4 lanes/edge x 2 edges/thread;
//     2 LDG.128/lane; split shfl_xor(2) combine; red.global.add.v4.
// ---------------------------------------------------------------------------

#define MAX_NODES 100000
#define F 16
#define TROWH 256                 // halves per node

__device__ __align__(512) __half g_table[(size_t)MAX_NODES * TROWH];
__device__ __align__(16) uint4 g_wfrag[2 * 8 * 32];   // [h][slot][lane], 8 KB

// memory halves order [lo, hi]
#define CVT_F16X2(u, lo, hi) \
    asm("cvt.rn.f16x2.f32 %0, %1, %2;" : "=r"(u) : "f"(hi), "f"(lo))

// ---------------------------------------------------------------------------
// Kernel 0: W fragments. 64 threads = 2 warps; warp h, lane l produce the
// fragment regs that (wrp&1)==h, lane l of the build kernel will consume.
//   uint4 slot i holds { bf0[2i], bf1[2i], bf0[2i+1], bf1[2i+1] }.
// ---------------------------------------------------------------------------
__global__ void wfrag_kernel(const float* __restrict__ w)
{
    int lane = threadIdx.x & 31;
    int h    = threadIdx.x >> 5;        // 0..1
    int k0   = (lane & 3) * 2;

    unsigned bf0[16], bf1[16];
#pragma unroll
    for (int t = 0; t < 16; t++) {
        int n    = h * 128 + t * 8 + (lane >> 2);
        int cell = n >> 4;
        int fo   = n & 15;
        const float* wc = w + cell * 256 + fo;
        float f0 = wc[k0 * 16];
        float f1 = wc[(k0 + 1) * 16];
        float f2 = wc[(k0 + 8) * 16];
        float f3 = wc[(k0 + 9) * 16];
        CVT_F16X2(bf0[t], f0, f1);
        CVT_F16X2(bf1[t], f2, f3);
    }
#pragma unroll
    for (int i = 0; i < 8; i++) {
        uint4 v;
        v.x = bf0[2 * i];
        v.y = bf1[2 * i];
        v.z = bf0[2 * i + 1];
        v.w = bf1[2 * i + 1];
        g_wfrag[(h * 8 + i) * 32 + lane] = v;
    }
}

// ---------------------------------------------------------------------------
// Kernel 1: tensor-core build + output zeroing.
// ---------------------------------------------------------------------------
#define OROW 528                    // padded smem row bytes
#define OTILE (16 * OROW)           // 8448 B per M-tile

__global__ __launch_bounds__(256) void build_table_kernel(
    const float* __restrict__ x,
    float4* __restrict__ out4,
    int out_n4,
    int n_nodes)
{
    __shared__ __align__(16) char smemA[4 * 512];     // 4 tiles x 16x16 fp16
    __shared__ __align__(16) char smemO[4 * OTILE];   // 33792 B

    int tid  = threadIdx.x;
    int lane = tid & 31;
    int wrp  = tid >> 5;
    int m    = wrp >> 1;            // M-tile slot 0..3
    int h    = wrp & 1;             // n-half: cols h*128 .. h*128+127

    // ---- zero the output buffer (replaces cudaMemsetAsync) ----
    {
        float4 z = make_float4(0.f, 0.f, 0.f, 0.f);
        for (int i = blockIdx.x * 256 + tid; i < out_n4;
             i += gridDim.x * 256)
            out4[i] = z;
    }

    // ---- fetch B fragments: 8 coalesced LDG.128 ----
    unsigned bf0[16], bf1[16];
    {
        const uint4* wb = g_wfrag + h * 8 * 32;
#pragma unroll
        for (int i = 0; i < 8; i++) {
            uint4 v = wb[i * 32 + lane];
            bf0[2 * i]     = v.x;
            bf1[2 * i]     = v.y;
            bf0[2 * i + 1] = v.z;
            bf1[2 * i + 1] = v.w;
        }
    }

    const float4* xf4 = reinterpret_cast<const float4*>(x);
    uint4* tb4 = reinterpret_cast<uint4*>(g_table);

    int n_tiles = (n_nodes + 15) >> 4;

    for (int bt = blockIdx.x * 4; bt < n_tiles; bt += gridDim.x * 4) {
        // ---- stage x tile: 64 nodes, fp32 -> fp16 ----
        {
            int nloc = tid >> 2;
            int part = tid & 3;
            int node = bt * 16 + nloc;
            uint2 v2 = make_uint2(0u, 0u);
            if (node < n_nodes) {
                float4 v = xf4[(size_t)node * 4 + part];
                CVT_F16X2(v2.x, v.x, v.y);
                CVT_F16X2(v2.y, v.z, v.w);
            }
            *reinterpret_cast<uint2*>(
                smemA + (nloc >> 4) * 512 + (nloc & 15) * 32 + part * 8) = v2;
        }
        __syncthreads();

        // ---- A fragments via ldmatrix.x4 ----
        unsigned a0, a1, a2, a3;
        {
            unsigned sa = (unsigned)__cvta_generic_to_shared(
                smemA + m * 512 + (lane & 15) * 32 + (lane >> 4) * 16);
            asm volatile(
                "ldmatrix.sync.aligned.m8n8.x4.shared.b16 {%0,%1,%2,%3}, [%4];"
                : "=r"(a0), "=r"(a1), "=r"(a2), "=r"(a3) : "r"(sa));
        }

        // ---- 16 HMMA in two halves of 8, pack + STS ----
        char* ob = smemO + m * OTILE;
        int row = lane >> 2;
#pragma unroll
        for (int half = 0; half < 2; half++) {
            float d[8][4];
#pragma unroll
            for (int tt = 0; tt < 8; tt++) {
                int t = half * 8 + tt;
                d[tt][0] = 0.f; d[tt][1] = 0.f; d[tt][2] = 0.f; d[tt][3] = 0.f;
                asm volatile(
                    "mma.sync.aligned.m16n8k16.row.col.f32.f16.f16.f32 "
                    "{%0,%1,%2,%3}, {%4,%5,%6,%7}, {%8,%9}, {%0,%1,%2,%3};"
                    : "+f"(d[tt][0]), "+f"(d[tt][1]),
                      "+f"(d[tt][2]), "+f"(d[tt][3])
                    : "r"(a0), "r"(a1), "r"(a2), "r"(a3),
                      "r"(bf0[t]), "r"(bf1[t]));
            }
#pragma unroll
            for (int tt = 0; tt < 8; tt++) {
                int t  = half * 8 + tt;
                int n0 = h * 128 + t * 8 + (lane & 3) * 2;
                unsigned p01, p23;
                CVT_F16X2(p01, d[tt][0], d[tt][1]);
                CVT_F16X2(p23, d[tt][2], d[tt][3]);
                *reinterpret_cast<unsigned*>(ob + row * OROW + n0 * 2) = p01;
                *reinterpret_cast<unsigned*>(ob + (row + 8) * OROW + n0 * 2) = p23;
            }
        }
        __syncthreads();

        // ---- coalesced readout: smemO -> g_table ----
        {
            int nloc = tid >> 2;
            int j0   = tid & 3;
            int node = bt * 16 + nloc;
            if (node < n_nodes) {
                const char* src = smemO + (nloc >> 4) * OTILE + (nloc & 15) * OROW;
#pragma unroll
                for (int jj = 0; jj < 8; jj++) {
                    int j = j0 + jj * 4;
                    uint4 val = *reinterpret_cast<const uint4*>(src + j * 16);
                    tb4[(size_t)node * 32 + j] = val;
                }
            }
        }
        __syncthreads();
    }
}

// ---------------------------------------------------------------------------
// Kernel 2: edge (proven 38.4us config).
// ---------------------------------------------------------------------------
#define EPB 128
__global__ __launch_bounds__(256) void edge_kernel(
    const int* __restrict__ ei,
    const float* __restrict__ attr,
    float* __restrict__ out,
    int n_edges)
{
    int tid = threadIdx.x;
    int sl  = tid & 3;
    int g   = tid >> 2;

    const uint4* tb = reinterpret_cast<const uint4*>(g_table);

    int  e[2];
    e[0] = (int)(blockIdx.x * EPB) + g;
    e[1] = e[0] + 64;
    bool val[2];
    int  row[2];
    uint4 u0[2], u1[2];
    float wa[2], wb[2];

#pragma unroll
    for (int i = 0; i < 2; i++) {
        val[i] = (e[i] < n_edges);
        int ec = val[i] ? e[i] : (n_edges - 1);

        row[i]   = ei[ec];
        int col  = ei[n_edges + ec];
        float2 a = reinterpret_cast<const float2*>(attr)[ec];

        float sx = fmaf(a.x, 1.5f, 1.5f);
        float sy = fmaf(a.y, 1.5f, 1.5f);
        float ixf = fminf(fmaxf(floorf(sx), 0.f), 2.f);
        float iyf = fminf(fmaxf(floorf(sy), 0.f), 2.f);
        float fx = sx - ixf;
        float fy = sy - iyf;
        int iu = (int)ixf;
        int iv = (int)iyf;

        float w11 = fx * fy;
        float w10 = fx - w11;
        float w01 = fy - w11;
        float w00 = 1.f - fx - fy + w11;

        wa[i] = (sl < 2) ? w00 : w01;   // u = iu
        wb[i] = (sl < 2) ? w10 : w11;   // u = iu+1

        size_t bi = (size_t)col * 32 + (iu * 4 + iv) * 2 + sl;
        u0[i] = tb[bi];
        u1[i] = tb[bi + 8];
    }

#pragma unroll
    for (int i = 0; i < 2; i++) {
        const __half2* h0 = reinterpret_cast<const __half2*>(&u0[i]);
        const __half2* h1 = reinterpret_cast<const __half2*>(&u1[i]);
        float p[8];
#pragma unroll
        for (int j = 0; j < 4; j++) {
            float2 f0 = __half22float2(h0[j]);
            float2 f1 = __half22float2(h1[j]);
            p[2 * j]     = fmaf(wa[i], f0.x, wb[i] * f1.x);
            p[2 * j + 1] = fmaf(wa[i], f0.y, wb[i] * f1.y);
        }
        bool hi = (sl & 2);
        float fin0, fin1, fin2, fin3;
        {
            float s0 = hi ? p[0] : p[4];
            float s1 = hi ? p[1] : p[5];
            float s2 = hi ? p[2] : p[6];
            float s3 = hi ? p[3] : p[7];
            float r0 = __shfl_xor_sync(0xffffffffu, s0, 2);
            float r1 = __shfl_xor_sync(0xffffffffu, s1, 2);
            float r2 = __shfl_xor_sync(0xffffffffu, s2, 2);
            float r3 = __shfl_xor_sync(0xffffffffu, s3, 2);
            fin0 = (hi ? p[4] : p[0]) + r0;
            fin1 = (hi ? p[5] : p[1]) + r1;
            fin2 = (hi ? p[6] : p[2]) + r2;
            fin3 = (hi ? p[7] : p[3]) + r3;
        }
        if (val[i]) {
            int quad = (sl & 1) * 2 + (sl >> 1);
            float* op = out + (size_t)row[i] * F + quad * 4;
            asm volatile("red.global.add.v4.f32 [%0], {%1, %2, %3, %4};"
                         :: "l"(op), "f"(fin0), "f"(fin1), "f"(fin2), "f"(fin3)
                         : "memory");
        }
    }
}

// ---------------------------------------------------------------------------
extern "C" void kernel_launch(void* const* d_in, const int* in_sizes, int n_in,
                              void* d_out, int out_size)
{
    const float* x    = (const float*)d_in[0];
    const int*   ei   = (const int*)d_in[1];
    const float* attr = (const float*)d_in[2];
    const float* w    = (const float*)d_in[3];
    float*       out  = (float*)d_out;

    int n_nodes = in_sizes[0] / F;       // 100000
    int n_edges = in_sizes[1] / 2;       // 1600000

    wfrag_kernel<<<1, 64>>>(w);

    int n_tiles  = (n_nodes + 15) / 16;       // 6250
    int bt_grid  = (n_tiles + 3) / 4;         // 1563 -> single iteration
    build_table_kernel<<<bt_grid, 256>>>(x, (float4*)out,
                                         out_size / 4, n_nodes);

    int ek_blocks = (n_edges + EPB - 1) / EPB;
    edge_kernel<<<ek_blocks, 256>>>(ei, attr, out, n_edges);
}

// round 16
// speedup vs baseline: 1.1719x; 1.0466x over previous
#include <cuda_runtime.h>
#include <cuda_fp16.h>
#include <cstdint>

// ---------------------------------------------------------------------------
// BasisConvLayer (mode='conv', linear hat basis 4x4, F_in=F_out=16)
//
// FP16 table  T[node][u:4][v:4][fout:16]  (512 B/node, 51 MB).
//   Kernel 0 (wfrag): HMMA B-fragments -> 8 KB global buffer. One thread per
//     output uint4 (512 threads): 8 independent LDG each -> ~1.5us.
//   Kernel 1 (build) = GEMM X[100K,16] @ W'[16,256] via mma.sync.m16n8k16;
//     grid covers all 16-node tiles in ONE iteration; fragments fetched with
//     8 coalesced LDG.128; also zeroes the output buffer.
//   Kernel 2 (edge): proven 38.4us floor config: 4 lanes/edge x 2
//     edges/thread; 2 LDG.128/lane; split shfl_xor(2); red.global.add.v4.
// ---------------------------------------------------------------------------

#define MAX_NODES 100000
#define F 16
#define TROWH 256                 // halves per node

__device__ __align__(512) __half g_table[(size_t)MAX_NODES * TROWH];
__device__ __align__(16) uint4 g_wfrag[2 * 8 * 32];   // [h][slot][lane], 8 KB

// memory halves order [lo, hi]
#define CVT_F16X2(u, lo, hi) \
    asm("cvt.rn.f16x2.f32 %0, %1, %2;" : "=r"(u) : "f"(hi), "f"(lo))

// ---------------------------------------------------------------------------
// Kernel 0: W fragments, flat. Thread t -> (h, slot i, lane); computes
//   uint4 { bf0[2i], bf1[2i], bf0[2i+1], bf1[2i+1] } with 8 independent LDGs.
// ---------------------------------------------------------------------------
__global__ __launch_bounds__(512) void wfrag_kernel(const float* __restrict__ w)
{
    int t    = threadIdx.x;            // 0..511
    int h    = t >> 8;                 // 0..1
    int idx  = t & 255;
    int slot = idx >> 5;               // 0..7
    int lane = idx & 31;
    int k0   = (lane & 3) * 2;

    uint4 v;
#pragma unroll
    for (int j = 0; j < 2; j++) {
        int tt   = slot * 2 + j;       // fragment index 0..15
        int n    = h * 128 + tt * 8 + (lane >> 2);
        int cell = n >> 4;
        int fo   = n & 15;
        const float* wc = w + cell * 256 + fo;
        float f0 = wc[k0 * 16];
        float f1 = wc[(k0 + 1) * 16];
        float f2 = wc[(k0 + 8) * 16];
        float f3 = wc[(k0 + 9) * 16];
        unsigned lo, hi;
        CVT_F16X2(lo, f0, f1);
        CVT_F16X2(hi, f2, f3);
        if (j == 0) { v.x = lo; v.y = hi; }
        else        { v.z = lo; v.w = hi; }
    }
    g_wfrag[(h * 8 + slot) * 32 + lane] = v;
}

// ---------------------------------------------------------------------------
// Kernel 1: tensor-core build + output zeroing.
// ---------------------------------------------------------------------------
#define OROW 528                    // padded smem row bytes
#define OTILE (16 * OROW)           // 8448 B per M-tile

__global__ __launch_bounds__(256) void build_table_kernel(
    const float* __restrict__ x,
    float4* __restrict__ out4,
    int out_n4,
    int n_nodes)
{
    __shared__ __align__(16) char smemA[4 * 512];     // 4 tiles x 16x16 fp16
    __shared__ __align__(16) char smemO[4 * OTILE];   // 33792 B

    int tid  = threadIdx.x;
    int lane = tid & 31;
    int wrp  = tid >> 5;
    int m    = wrp >> 1;            // M-tile slot 0..3
    int h    = wrp & 1;             // n-half: cols h*128 .. h*128+127

    // ---- zero the output buffer (replaces cudaMemsetAsync) ----
    {
        float4 z = make_float4(0.f, 0.f, 0.f, 0.f);
        for (int i = blockIdx.x * 256 + tid; i < out_n4;
             i += gridDim.x * 256)
            out4[i] = z;
    }

    // ---- fetch B fragments: 8 coalesced LDG.128 ----
    unsigned bf0[16], bf1[16];
    {
        const uint4* wb = g_wfrag + h * 8 * 32;
#pragma unroll
        for (int i = 0; i < 8; i++) {
            uint4 v = wb[i * 32 + lane];
            bf0[2 * i]     = v.x;
            bf1[2 * i]     = v.y;
            bf0[2 * i + 1] = v.z;
            bf1[2 * i + 1] = v.w;
        }
    }

    const float4* xf4 = reinterpret_cast<const float4*>(x);
    uint4* tb4 = reinterpret_cast<uint4*>(g_table);

    int n_tiles = (n_nodes + 15) >> 4;

    for (int bt = blockIdx.x * 4; bt < n_tiles; bt += gridDim.x * 4) {
        // ---- stage x tile: 64 nodes, fp32 -> fp16 ----
        {
            int nloc = tid >> 2;
            int part = tid & 3;
            int node = bt * 16 + nloc;
            uint2 v2 = make_uint2(0u, 0u);
            if (node < n_nodes) {
                float4 v = xf4[(size_t)node * 4 + part];
                CVT_F16X2(v2.x, v.x, v.y);
                CVT_F16X2(v2.y, v.z, v.w);
            }
            *reinterpret_cast<uint2*>(
                smemA + (nloc >> 4) * 512 + (nloc & 15) * 32 + part * 8) = v2;
        }
        __syncthreads();

        // ---- A fragments via ldmatrix.x4 ----
        unsigned a0, a1, a2, a3;
        {
            unsigned sa = (unsigned)__cvta_generic_to_shared(
                smemA + m * 512 + (lane & 15) * 32 + (lane >> 4) * 16);
            asm volatile(
                "ldmatrix.sync.aligned.m8n8.x4.shared.b16 {%0,%1,%2,%3}, [%4];"
                : "=r"(a0), "=r"(a1), "=r"(a2), "=r"(a3) : "r"(sa));
        }

        // ---- 16 HMMA in two halves of 8, pack + STS ----
        char* ob = smemO + m * OTILE;
        int row = lane >> 2;
#pragma unroll
        for (int half = 0; half < 2; half++) {
            float d[8][4];
#pragma unroll
            for (int tt = 0; tt < 8; tt++) {
                int t = half * 8 + tt;
                d[tt][0] = 0.f; d[tt][1] = 0.f; d[tt][2] = 0.f; d[tt][3] = 0.f;
                asm volatile(
                    "mma.sync.aligned.m16n8k16.row.col.f32.f16.f16.f32 "
                    "{%0,%1,%2,%3}, {%4,%5,%6,%7}, {%8,%9}, {%0,%1,%2,%3};"
                    : "+f"(d[tt][0]), "+f"(d[tt][1]),
                      "+f"(d[tt][2]), "+f"(d[tt][3])
                    : "r"(a0), "r"(a1), "r"(a2), "r"(a3),
                      "r"(bf0[t]), "r"(bf1[t]));
            }
#pragma unroll
            for (int tt = 0; tt < 8; tt++) {
                int t  = half * 8 + tt;
                int n0 = h * 128 + t * 8 + (lane & 3) * 2;
                unsigned p01, p23;
                CVT_F16X2(p01, d[tt][0], d[tt][1]);
                CVT_F16X2(p23, d[tt][2], d[tt][3]);
                *reinterpret_cast<unsigned*>(ob + row * OROW + n0 * 2) = p01;
                *reinterpret_cast<unsigned*>(ob + (row + 8) * OROW + n0 * 2) = p23;
            }
        }
        __syncthreads();

        // ---- coalesced readout: smemO -> g_table ----
        {
            int nloc = tid >> 2;
            int j0   = tid & 3;
            int node = bt * 16 + nloc;
            if (node < n_nodes) {
                const char* src = smemO + (nloc >> 4) * OTILE + (nloc & 15) * OROW;
#pragma unroll
                for (int jj = 0; jj < 8; jj++) {
                    int j = j0 + jj * 4;
                    uint4 val = *reinterpret_cast<const uint4*>(src + j * 16);
                    tb4[(size_t)node * 32 + j] = val;
                }
            }
        }
        __syncthreads();
    }
}

// ---------------------------------------------------------------------------
// Kernel 2: edge (proven 38.4us config).
// ---------------------------------------------------------------------------
#define EPB 128
__global__ __launch_bounds__(256) void edge_kernel(
    const int* __restrict__ ei,
    const float* __restrict__ attr,
    float* __restrict__ out,
    int n_edges)
{
    int tid = threadIdx.x;
    int sl  = tid & 3;
    int g   = tid >> 2;

    const uint4* tb = reinterpret_cast<const uint4*>(g_table);

    int  e[2];
    e[0] = (int)(blockIdx.x * EPB) + g;
    e[1] = e[0] + 64;
    bool val[2];
    int  row[2];
    uint4 u0[2], u1[2];
    float wa[2], wb[2];

#pragma unroll
    for (int i = 0; i < 2; i++) {
        val[i] = (e[i] < n_edges);
        int ec = val[i] ? e[i] : (n_edges - 1);

        row[i]   = ei[ec];
        int col  = ei[n_edges + ec];
        float2 a = reinterpret_cast<const float2*>(attr)[ec];

        float sx = fmaf(a.x, 1.5f, 1.5f);
        float sy = fmaf(a.y, 1.5f, 1.5f);
        float ixf = fminf(fmaxf(floorf(sx), 0.f), 2.f);
        float iyf = fminf(fmaxf(floorf(sy), 0.f), 2.f);
        float fx = sx - ixf;
        float fy = sy - iyf;
        int iu = (int)ixf;
        int iv = (int)iyf;

        float w11 = fx * fy;
        float w10 = fx - w11;
        float w01 = fy - w11;
        float w00 = 1.f - fx - fy + w11;

        wa[i] = (sl < 2) ? w00 : w01;   // u = iu
        wb[i] = (sl < 2) ? w10 : w11;   // u = iu+1

        size_t bi = (size_t)col * 32 + (iu * 4 + iv) * 2 + sl;
        u0[i] = tb[bi];
        u1[i] = tb[bi + 8];
    }

#pragma unroll
    for (int i = 0; i < 2; i++) {
        const __half2* h0 = reinterpret_cast<const __half2*>(&u0[i]);
        const __half2* h1 = reinterpret_cast<const __half2*>(&u1[i]);
        float p[8];
#pragma unroll
        for (int j = 0; j < 4; j++) {
            float2 f0 = __half22float2(h0[j]);
            float2 f1 = __half22float2(h1[j]);
            p[2 * j]     = fmaf(wa[i], f0.x, wb[i] * f1.x);
            p[2 * j + 1] = fmaf(wa[i], f0.y, wb[i] * f1.y);
        }
        bool hi = (sl & 2);
        float fin0, fin1, fin2, fin3;
        {
            float s0 = hi ? p[0] : p[4];
            float s1 = hi ? p[1] : p[5];
            float s2 = hi ? p[2] : p[6];
            float s3 = hi ? p[3] : p[7];
            float r0 = __shfl_xor_sync(0xffffffffu, s0, 2);
            float r1 = __shfl_xor_sync(0xffffffffu, s1, 2);
            float r2 = __shfl_xor_sync(0xffffffffu, s2, 2);
            float r3 = __shfl_xor_sync(0xffffffffu, s3, 2);
            fin0 = (hi ? p[4] : p[0]) + r0;
            fin1 = (hi ? p[5] : p[1]) + r1;
            fin2 = (hi ? p[6] : p[2]) + r2;
            fin3 = (hi ? p[7] : p[3]) + r3;
        }
        if (val[i]) {
            int quad = (sl & 1) * 2 + (sl >> 1);
            float* op = out + (size_t)row[i] * F + quad * 4;
            asm volatile("red.global.add.v4.f32 [%0], {%1, %2, %3, %4};"
                         :: "l"(op), "f"(fin0), "f"(fin1), "f"(fin2), "f"(fin3)
                         : "memory");
        }
    }
}

// ---------------------------------------------------------------------------
extern "C" void kernel_launch(void* const* d_in, const int* in_sizes, int n_in,
                              void* d_out, int out_size)
{
    const float* x    = (const float*)d_in[0];
    const int*   ei   = (const int*)d_in[1];
    const float* attr = (const float*)d_in[2];
    const float* w    = (const float*)d_in[3];
    float*       out  = (float*)d_out;

    int n_nodes = in_sizes[0] / F;       // 100000
    int n_edges = in_sizes[1] / 2;       // 1600000

    wfrag_kernel<<<1, 512>>>(w);

    int n_tiles  = (n_nodes + 15) / 16;       // 6250
    int bt_grid  = (n_tiles + 3) / 4;         // 1563 -> single iteration
    build_table_kernel<<<bt_grid, 256>>>(x, (float4*)out,
                                         out_size / 4, n_nodes);

    int ek_blocks = (n_edges + EPB - 1) / EPB;
    edge_kernel<<<ek_blocks, 256>>>(ei, attr, out, n_edges);
}